// round 11
// baseline (speedup 1.0000x reference)
#include <cuda_runtime.h>
#include <cuda_fp16.h>
#include <cstdint>
#include <string.h>
#include <math.h>

#define B_    8
#define C_    512
#define H_    96
#define W_    96
#define HW_   9216
#define NTOK  73728
#define IMGN  37748736
#define NHEAD 8
#define DH    64
#define WN    262144          // C_*C_ = 2^18

// Scratch buffers
__device__ __half g_hv[IMGN];
__device__ __half g_hA[IMGN];
__device__ __half g_hB[IMGN];
__device__ __half g_hC[IMGN];
__device__ __half g_hD[IMGN];
__device__ __half g_hE[IMGN];
__device__ __half g_wh[7 * WN];

// ===========================================================================
// PTX helpers
// ===========================================================================
__device__ __forceinline__ uint32_t smem_u32(const void* p) {
    uint32_t a;
    asm("{ .reg .u64 t; cvta.to.shared.u64 t, %1; cvt.u32.u64 %0, t; }"
        : "=r"(a) : "l"(p));
    return a;
}
#define CP_ASYNC16(dst, src) \
    asm volatile("cp.async.cg.shared.global [%0], [%1], 16;" :: "r"(dst), "l"(src))
#define CP_COMMIT() asm volatile("cp.async.commit_group;" ::: "memory")
#define CP_WAIT0()  asm volatile("cp.async.wait_group 0;" ::: "memory")

#define LDSM_X4(r0, r1, r2, r3, addr) \
    asm volatile("ldmatrix.sync.aligned.m8n8.x4.shared.b16 {%0,%1,%2,%3}, [%4];" \
        : "=r"(r0), "=r"(r1), "=r"(r2), "=r"(r3) : "r"(addr))

#define LDSM_X4_TRANS(r0, r1, r2, r3, addr) \
    asm volatile("ldmatrix.sync.aligned.m8n8.x4.trans.shared.b16 {%0,%1,%2,%3}, [%4];" \
        : "=r"(r0), "=r"(r1), "=r"(r2), "=r"(r3) : "r"(addr))

__device__ __forceinline__ void mma_f16(float* d, const uint32_t* a, const uint32_t* b) {
    asm volatile(
        "mma.sync.aligned.m16n8k16.row.col.f32.f16.f16.f32 "
        "{%0,%1,%2,%3}, {%4,%5,%6,%7}, {%8,%9}, {%0,%1,%2,%3};"
        : "+f"(d[0]), "+f"(d[1]), "+f"(d[2]), "+f"(d[3])
        : "r"(a[0]), "r"(a[1]), "r"(a[2]), "r"(a[3]), "r"(b[0]), "r"(b[1]));
}

__device__ __forceinline__ uint32_t pack2h(float x, float y) {
    __half2 h = __floats2half2_rn(x, y);
    uint32_t u;
    memcpy(&u, &h, 4);
    return u;
}

// ===========================================================================
// All weights fp32 -> fp16 in ONE launch.
// Slots: 0=Wk 1=Wv 2=crWv (fused GEMM B) | 3=Wo 4=crWq 5=crWo 6=pw
// ===========================================================================
__global__ void k_w2h_all(const float* __restrict__ wk, const float* __restrict__ wv,
                          const float* __restrict__ cwv, const float* __restrict__ wo,
                          const float* __restrict__ cwq, const float* __restrict__ cwo,
                          const float* __restrict__ pw, __half* __restrict__ o) {
    int i = blockIdx.x * 256 + threadIdx.x;
    if (i >= 7 * WN) return;
    int slot = i >> 18, off = i & (WN - 1);
    const float* src;
    switch (slot) {
        case 0: src = wk;  break;
        case 1: src = wv;  break;
        case 2: src = cwv; break;
        case 3: src = wo;  break;
        case 4: src = cwq; break;
        case 5: src = cwo; break;
        default: src = pw; break;
    }
    o[i] = __float2half(src[off]);
}

// ===========================================================================
// Transpose bchw(f32) -> nhc(half)
// ===========================================================================
__global__ void k_bchw_to_nhc(const float* __restrict__ src, __half* __restrict__ dsth) {
    __shared__ float tile[32][33];
    int bh = blockIdx.z;
    int b = bh / H_, h = bh % H_;
    int c0 = blockIdx.y * 32;
    int w0 = blockIdx.x * 32;
    int tx = threadIdx.x, ty = threadIdx.y;
#pragma unroll
    for (int k = 0; k < 4; ++k) {
        int c = c0 + ty + k * 8;
        tile[ty + k * 8][tx] = src[(((size_t)b * C_ + c) * H_ + h) * W_ + w0 + tx];
    }
    __syncthreads();
#pragma unroll
    for (int k = 0; k < 4; ++k) {
        int w = w0 + ty + k * 8;
        dsth[(((size_t)b * W_ + w) * H_ + h) * C_ + c0 + tx] =
            __float2half(tile[tx][ty + k * 8]);
    }
}

// ===========================================================================
// Transpose nhc(half) -> bchw-flat(half)  (the q_view reshape)
// ===========================================================================
__global__ void k_nhc_to_bchw_h(const __half* __restrict__ src, __half* __restrict__ dst) {
    __shared__ __half tile[32][34];
    int bh = blockIdx.z;
    int b = bh / H_, h = bh % H_;
    int c0 = blockIdx.y * 32;
    int w0 = blockIdx.x * 32;
    int tx = threadIdx.x, ty = threadIdx.y;
#pragma unroll
    for (int k = 0; k < 4; ++k) {
        int w = w0 + ty + k * 8;
        tile[ty + k * 8][tx] = src[(((size_t)b * W_ + w) * H_ + h) * C_ + c0 + tx];
    }
    __syncthreads();
#pragma unroll
    for (int k = 0; k < 4; ++k) {
        int c = c0 + ty + k * 8;
        dst[(((size_t)b * C_ + c) * H_ + h) * W_ + w0 + tx] = tile[tx][ty + k * 8];
    }
}

// ===========================================================================
// fp16 mma GEMM. CTA 128x128, BK=64, 2-stage cp.async (3 CTAs/SM), ldmatrix.
// MODE 0: plain ->half
// MODE 2: +bias32[n] ->half
// MODE 3: relu6 + CR(half, same token order) -> fp32 BCHW scatter
// MODE 6: fused N=1536 [K|V|KV]: seg0 -> Cv + half residual(extra), seg1->C1, seg2->C2
// ===========================================================================
#define BKH    64
#define SLDH   72
#define TILEH  (128 * SLDH)
#define STAGEB (2 * TILEH * 2)
#define GSMEM  (2 * STAGEB)            // 73728 B -> 3 CTAs/SM

__device__ __forceinline__ void load_tile_h(
    const __half* __restrict__ A, const __half* __restrict__ Wt,
    int m0, int n0, int kt, uint32_t sa, uint32_t sb, int tid)
{
#pragma unroll
    for (int it = 0; it < 4; ++it) {
        int c = it * 256 + tid;
        int row = c >> 3;
        int seg = c & 7;
        CP_ASYNC16(sa + (row * SLDH + seg * 8) * 2,
                   A + (size_t)(m0 + row) * 512 + kt + seg * 8);
        CP_ASYNC16(sb + (row * SLDH + seg * 8) * 2,
                   Wt + (size_t)(n0 + row) * 512 + kt + seg * 8);
    }
}

template <int MODE>
__global__ __launch_bounds__(256, 3) void k_hgemm(
    const __half* __restrict__ A, const __half* __restrict__ Wt,
    void* __restrict__ Cv, const void* __restrict__ extra,
    void* __restrict__ C1, void* __restrict__ C2)
{
    extern __shared__ char smraw[];
    const uint32_t s0 = smem_u32(smraw);

    const int tid = threadIdx.x;
    const int m0 = blockIdx.y * 128;
    const int n0 = blockIdx.x * 128;
    const int wid = tid >> 5, lane = tid & 31;
    const int mw = (wid & 3) * 32;
    const int nw = (wid >> 2) * 64;
    const int g = lane >> 2, tig = lane & 3;

    uint32_t aoff[2], boff[4];
#pragma unroll
    for (int i = 0; i < 2; ++i)
        aoff[i] = ((mw + i * 16 + (lane & 15)) * SLDH + (lane >> 4) * 8) * 2;
#pragma unroll
    for (int jp = 0; jp < 4; ++jp)
        boff[jp] = (uint32_t)(TILEH * 2) +
                   ((nw + jp * 16 + ((lane & 7) | ((lane >> 4) << 3))) * SLDH +
                    ((lane >> 3) & 1) * 8) * 2;

    float d[2][8][4];
#pragma unroll
    for (int i = 0; i < 2; ++i)
#pragma unroll
        for (int j = 0; j < 8; ++j)
#pragma unroll
            for (int q = 0; q < 4; ++q) d[i][j][q] = 0.f;

    load_tile_h(A, Wt, m0, n0, 0, s0, s0 + TILEH * 2, tid);
    CP_COMMIT();

#pragma unroll 1
    for (int t = 0; t < 8; ++t) {
        CP_WAIT0();
        __syncthreads();
        if (t + 1 < 8) {
            uint32_t sb = s0 + ((t + 1) & 1) * STAGEB;
            load_tile_h(A, Wt, m0, n0, (t + 1) * BKH, sb, sb + TILEH * 2, tid);
            CP_COMMIT();
        }
        const uint32_t st = s0 + (t & 1) * STAGEB;
#pragma unroll
        for (int kk = 0; kk < 4; ++kk) {
            const uint32_t kb = kk * 32;
            uint32_t af[2][4], bf[8][2];
#pragma unroll
            for (int i = 0; i < 2; ++i)
                LDSM_X4(af[i][0], af[i][1], af[i][2], af[i][3], st + aoff[i] + kb);
#pragma unroll
            for (int jp = 0; jp < 4; ++jp)
                LDSM_X4(bf[2 * jp][0], bf[2 * jp][1], bf[2 * jp + 1][0], bf[2 * jp + 1][1],
                        st + boff[jp] + kb);
#pragma unroll
            for (int i = 0; i < 2; ++i)
#pragma unroll
                for (int j = 0; j < 8; ++j)
                    mma_f16(d[i][j], af[i], bf[j]);
        }
    }

    // --- Epilogue ---
    __half* m6out = nullptr;
    bool m6res = false;
    if (MODE == 6) {
        int seg = n0 >> 9;
        m6out = (seg == 0) ? (__half*)Cv : (seg == 1) ? (__half*)C1 : (__half*)C2;
        m6res = (seg == 0);
    }

#pragma unroll
    for (int i = 0; i < 2; ++i) {
#pragma unroll
        for (int half_ = 0; half_ < 2; ++half_) {
            int m = m0 + mw + i * 16 + g + half_ * 8;
            if (MODE == 3) {
                int bb = m / HW_;
                int srow = m - bb * HW_;
                const __half* crp = (const __half*)extra + (size_t)m * 512;
                float* outp = (float*)Cv + (size_t)bb * 512 * HW_ + srow;
#pragma unroll
                for (int j = 0; j < 8; ++j) {
                    int nn = n0 + nw + j * 8 + 2 * tig;
                    uint32_t cr2 = *(const uint32_t*)(crp + nn);
                    __half2 ch; memcpy(&ch, &cr2, 4);
                    float v0 = fminf(fmaxf(d[i][j][half_ * 2 + 0], 0.f), 6.f) + __low2float(ch);
                    float v1 = fminf(fmaxf(d[i][j][half_ * 2 + 1], 0.f), 6.f) + __high2float(ch);
                    outp[(size_t)nn * HW_] = v0;
                    outp[(size_t)(nn + 1) * HW_] = v1;
                }
            } else if (MODE == 6) {
                __half* cp = m6out + (size_t)m * 512;
                const __half* rp = (const __half*)extra + (size_t)m * 512;
#pragma unroll
                for (int j = 0; j < 8; ++j) {
                    int nn = n0 + nw + j * 8 + 2 * tig;
                    int col = nn & 511;
                    float v0 = d[i][j][half_ * 2 + 0];
                    float v1 = d[i][j][half_ * 2 + 1];
                    if (m6res) {
                        uint32_t r2 = *(const uint32_t*)(rp + col);
                        __half2 rh; memcpy(&rh, &r2, 4);
                        v0 += __low2float(rh);
                        v1 += __high2float(rh);
                    }
                    *(uint32_t*)(cp + col) = pack2h(v0, v1);
                }
            } else {
                __half* cp = (__half*)Cv + (size_t)m * 512;
                const float* ep = (const float*)extra;
#pragma unroll
                for (int j = 0; j < 8; ++j) {
                    int nn = n0 + nw + j * 8 + 2 * tig;
                    float v0 = d[i][j][half_ * 2 + 0];
                    float v1 = d[i][j][half_ * 2 + 1];
                    if (MODE == 2) { v0 += ep[nn]; v1 += ep[nn + 1]; }
                    *(uint32_t*)(cp + nn) = pack2h(v0, v1);
                }
            }
        }
    }
}

// ===========================================================================
// Flash-style fp16 attention. V loaded row-major via cp.async and read with
// ldmatrix.trans (no manual transpose). 5 CTAs/SM.
// PERM=true permutes OUTPUT tokens bwh->bhw (free, per-row contiguous).
// ===========================================================================
#define AQLD 72
#define ATTN_SMEM (3 * 96 * AQLD * 2)   // 41472 B

template <bool PERM>
__global__ __launch_bounds__(192, 5) void k_attn_h(
    const __half* __restrict__ Q, const __half* __restrict__ Kt,
    const __half* __restrict__ Vt, __half* __restrict__ O)
{
    extern __shared__ char smraw[];
    const uint32_t sQ = smem_u32(smraw);
    const uint32_t sK = sQ + 96 * AQLD * 2;
    const uint32_t sV = sK + 96 * AQLD * 2;

    const int tid = threadIdx.x;
    const int n = blockIdx.x >> 3;
    const int hd = blockIdx.x & 7;
    const size_t base = (size_t)n * 96 * 512 + hd * DH;

    size_t obase, orow;
    if (PERM) {
        int b = n / 96, w = n - (n / 96) * 96;
        obase = (size_t)b * 9216 * 512 + (size_t)w * 512 + hd * DH;
        orow = 96 * 512;
    } else {
        obase = base;
        orow = 512;
    }

    // Q, K, V all via cp.async (row-major 96 x 64 halves each)
    for (int i = tid; i < 96 * 8; i += 192) {
        int r = i >> 3, seg = i & 7;
        size_t go = base + (size_t)r * 512 + seg * 8;
        uint32_t so = (r * AQLD + seg * 8) * 2;
        CP_ASYNC16(sQ + so, Q + go);
        CP_ASYNC16(sK + so, Kt + go);
        CP_ASYNC16(sV + so, Vt + go);
    }
    CP_COMMIT();
    CP_WAIT0();
    __syncthreads();

    const int wid = tid / 32, lane = tid % 32;
    const int g = lane >> 2, tig = lane & 3;
    const int m0 = wid * 16;

    const uint32_t aAddr = sQ + ((m0 + (lane & 15)) * AQLD + (lane >> 4) * 8) * 2;
    const uint32_t bRow = (lane & 7) | ((lane >> 4) << 3);
    const uint32_t bCol = ((lane >> 3) & 1) * 8;
    // V trans-pattern: lane -> row (key) lane&15, col block (lane>>4)*8
    const uint32_t vAddr = sV + (((lane & 15) * AQLD) + (lane >> 4) * 8) * 2;

    // --- QK^T ---
    float dS[12][4];
#pragma unroll
    for (int j = 0; j < 12; ++j)
#pragma unroll
        for (int q = 0; q < 4; ++q) dS[j][q] = 0.f;

#pragma unroll
    for (int kk = 0; kk < 4; ++kk) {
        uint32_t af[4];
        LDSM_X4(af[0], af[1], af[2], af[3], aAddr + kk * 32);
#pragma unroll
        for (int jp = 0; jp < 6; ++jp) {
            uint32_t b0, b1, b2, b3;
            LDSM_X4(b0, b1, b2, b3,
                    sK + ((jp * 16 + bRow) * AQLD + bCol) * 2 + kk * 32);
            uint32_t bA[2] = {b0, b1}, bB[2] = {b2, b3};
            mma_f16(dS[2 * jp], af, bA);
            mma_f16(dS[2 * jp + 1], af, bB);
        }
    }

    // --- register softmax ---
    float mx0 = -1e30f, mx1 = -1e30f;
#pragma unroll
    for (int j = 0; j < 12; ++j) {
        dS[j][0] *= 0.125f; dS[j][1] *= 0.125f;
        dS[j][2] *= 0.125f; dS[j][3] *= 0.125f;
        mx0 = fmaxf(mx0, fmaxf(dS[j][0], dS[j][1]));
        mx1 = fmaxf(mx1, fmaxf(dS[j][2], dS[j][3]));
    }
    mx0 = fmaxf(mx0, __shfl_xor_sync(0xffffffffu, mx0, 1));
    mx0 = fmaxf(mx0, __shfl_xor_sync(0xffffffffu, mx0, 2));
    mx1 = fmaxf(mx1, __shfl_xor_sync(0xffffffffu, mx1, 1));
    mx1 = fmaxf(mx1, __shfl_xor_sync(0xffffffffu, mx1, 2));
    float s0 = 0.f, s1 = 0.f;
#pragma unroll
    for (int j = 0; j < 12; ++j) {
        dS[j][0] = __expf(dS[j][0] - mx0); dS[j][1] = __expf(dS[j][1] - mx0);
        dS[j][2] = __expf(dS[j][2] - mx1); dS[j][3] = __expf(dS[j][3] - mx1);
        s0 += dS[j][0] + dS[j][1];
        s1 += dS[j][2] + dS[j][3];
    }
    s0 += __shfl_xor_sync(0xffffffffu, s0, 1);
    s0 += __shfl_xor_sync(0xffffffffu, s0, 2);
    s1 += __shfl_xor_sync(0xffffffffu, s1, 1);
    s1 += __shfl_xor_sync(0xffffffffu, s1, 2);
    const float i0 = 1.f / s0, i1 = 1.f / s1;

    uint32_t aP[6][4];
#pragma unroll
    for (int kk = 0; kk < 6; ++kk) {
        aP[kk][0] = pack2h(dS[2 * kk][0] * i0, dS[2 * kk][1] * i0);
        aP[kk][1] = pack2h(dS[2 * kk][2] * i1, dS[2 * kk][3] * i1);
        aP[kk][2] = pack2h(dS[2 * kk + 1][0] * i0, dS[2 * kk + 1][1] * i0);
        aP[kk][3] = pack2h(dS[2 * kk + 1][2] * i1, dS[2 * kk + 1][3] * i1);
    }

    // --- PV: B frags via ldmatrix.trans on row-major V ---
    float dO[8][4];
#pragma unroll
    for (int j = 0; j < 8; ++j)
#pragma unroll
        for (int q = 0; q < 4; ++q) dO[j][q] = 0.f;

#pragma unroll
    for (int kk = 0; kk < 6; ++kk) {
        uint32_t bf[8][2];
#pragma unroll
        for (int jp = 0; jp < 4; ++jp)
            LDSM_X4_TRANS(bf[2 * jp][0], bf[2 * jp][1], bf[2 * jp + 1][0], bf[2 * jp + 1][1],
                          vAddr + (kk * 16 * AQLD + jp * 16) * 2);
#pragma unroll
        for (int j = 0; j < 8; ++j)
            mma_f16(dO[j], aP[kk], bf[j]);
    }

#pragma unroll
    for (int j = 0; j < 8; ++j) {
        int col = j * 8 + 2 * tig;
        *(uint32_t*)(O + obase + (size_t)(m0 + g) * orow + col) =
            pack2h(dO[j][0], dO[j][1]);
        *(uint32_t*)(O + obase + (size_t)(m0 + g + 8) * orow + col) =
            pack2h(dO[j][2], dO[j][3]);
    }
}

// ===========================================================================
// Depthwise 3x3 + BN -> token-major half, coalesced writes
// ===========================================================================
__global__ __launch_bounds__(256) void k_dwconv2(
    const float* __restrict__ x, const float* __restrict__ wgt,
    const float* __restrict__ bg, const float* __restrict__ bb_,
    const float* __restrict__ bm, const float* __restrict__ bv,
    __half* __restrict__ y)
{
    __shared__ float taps[16][9];
    __shared__ float psc[16], pmm[16], pbb[16];
    __shared__ uint32_t sOut[256 * 9];

    const int tid = threadIdx.x;
    const int c0 = blockIdx.y * 16, b = blockIdx.z, s0 = blockIdx.x * 256;

    if (tid < 16 * 9) taps[tid / 9][tid % 9] = wgt[(c0 + tid / 9) * 9 + tid % 9];
    else if (tid < 160) {
        int ch = tid - 144;
        psc[ch] = bg[c0 + ch] * rsqrtf(bv[c0 + ch] + 1e-5f);
        pmm[ch] = bm[c0 + ch];
        pbb[ch] = bb_[c0 + ch];
    }
    __syncthreads();

    const int s = s0 + tid;
    const int h = s / W_, w = s - (s / W_) * W_;
    const bool hm = h > 0, hp = h < H_ - 1, wm = w > 0, wp = w < W_ - 1;

    float acc[16];
#pragma unroll
    for (int ch = 0; ch < 16; ++ch) {
        const float* xc = x + ((size_t)b * C_ + c0 + ch) * HW_ + s;
        const float* tp = taps[ch];
        float a = xc[0] * tp[4];
        if (wm) a = fmaf(xc[-1], tp[3], a);
        if (wp) a = fmaf(xc[1],  tp[5], a);
        if (hm) {
            a = fmaf(xc[-W_], tp[1], a);
            if (wm) a = fmaf(xc[-W_ - 1], tp[0], a);
            if (wp) a = fmaf(xc[-W_ + 1], tp[2], a);
        }
        if (hp) {
            a = fmaf(xc[W_], tp[7], a);
            if (wm) a = fmaf(xc[W_ - 1], tp[6], a);
            if (wp) a = fmaf(xc[W_ + 1], tp[8], a);
        }
        acc[ch] = (a - pmm[ch]) * psc[ch] + pbb[ch];
    }
#pragma unroll
    for (int q = 0; q < 8; ++q)
        sOut[tid * 9 + q] = pack2h(acc[2 * q], acc[2 * q + 1]);
    __syncthreads();

    uint32_t* y32 = (uint32_t*)y;
    const size_t rowbase = ((size_t)b * HW_ + s0) * 256 + (c0 >> 1);
#pragma unroll
    for (int it = 0; it < 8; ++it) {
        int i = it * 256 + tid;
        int token = i >> 3, q = i & 7;
        y32[rowbase + (size_t)token * 256 + q] = sOut[token * 9 + q];
    }
}

// ===========================================================================
// Launch
// ===========================================================================
extern "C" void kernel_launch(void* const* d_in, const int* in_sizes, int n_in,
                              void* d_out, int out_size)
{
    const float* x      = (const float*)d_in[0];
    const float* msa_Wk = (const float*)d_in[1];
    const float* msa_Wv = (const float*)d_in[2];
    const float* msa_Wo = (const float*)d_in[3];
    const float* cr_Wq  = (const float*)d_in[4];
    const float* cr_bq  = (const float*)d_in[5];
    const float* cr_Wv  = (const float*)d_in[6];
    const float* cr_Wo  = (const float*)d_in[7];
    const float* dw_w   = (const float*)d_in[8];
    const float* bn_g   = (const float*)d_in[9];
    const float* bn_b   = (const float*)d_in[10];
    const float* bn_m   = (const float*)d_in[11];
    const float* bn_v   = (const float*)d_in[12];
    const float* pw_w   = (const float*)d_in[13];
    float* out = (float*)d_out;

    __half *hv, *hA, *hB, *hC, *hD, *hE, *wh;
    cudaGetSymbolAddress((void**)&hv, g_hv);
    cudaGetSymbolAddress((void**)&hA, g_hA);
    cudaGetSymbolAddress((void**)&hB, g_hB);
    cudaGetSymbolAddress((void**)&hC, g_hC);
    cudaGetSymbolAddress((void**)&hD, g_hD);
    cudaGetSymbolAddress((void**)&hE, g_hE);
    cudaGetSymbolAddress((void**)&wh, g_wh);

    cudaFuncSetAttribute(k_hgemm<0>, cudaFuncAttributeMaxDynamicSharedMemorySize, GSMEM);
    cudaFuncSetAttribute(k_hgemm<2>, cudaFuncAttributeMaxDynamicSharedMemorySize, GSMEM);
    cudaFuncSetAttribute(k_hgemm<3>, cudaFuncAttributeMaxDynamicSharedMemorySize, GSMEM);
    cudaFuncSetAttribute(k_hgemm<6>, cudaFuncAttributeMaxDynamicSharedMemorySize, GSMEM);
    cudaFuncSetAttribute(k_attn_h<false>, cudaFuncAttributeMaxDynamicSharedMemorySize, ATTN_SMEM);
    cudaFuncSetAttribute(k_attn_h<true>,  cudaFuncAttributeMaxDynamicSharedMemorySize, ATTN_SMEM);

    // 0. weights -> half
    k_w2h_all<<<(7 * WN + 255) / 256, 256>>>(msa_Wk, msa_Wv, cr_Wv, msa_Wo,
                                             cr_Wq, cr_Wo, pw_w, wh);

    dim3 tgrid(3, 16, B_ * H_), tblk(32, 8);
    dim3 ggrid(4, NTOK / 128), gblk(256);
    dim3 g6grid(12, NTOK / 128);
    dim3 dgrid(HW_ / 256, C_ / 16, B_);

    // 1. vqk = permute(x) (half)
    k_bchw_to_nhc<<<tgrid, tblk>>>(x, hv);
    // 2. fused [K|V|KV] = vqk @ [Wk|Wv|crWv]^T (K += vqk residual)
    k_hgemm<6><<<g6grid, gblk, GSMEM>>>(hv, wh, hA, hv, hB, hC);
    // 3. attn(vqk, K, V) -> hD (nhc)
    k_attn_h<false><<<B_ * W_ * NHEAD, 192, ATTN_SMEM>>>(hv, hA, hB, hD);
    // 4. O = attn@Wo^T -> hE (nhc)
    k_hgemm<0><<<ggrid, gblk, GSMEM>>>(hD, wh + 3 * WN, hE, nullptr, nullptr, nullptr);
    // 5. q_view = nhc->bchw(hE) -> hA
    k_nhc_to_bchw_h<<<tgrid, tblk>>>(hE, hA);
    // 6. Q2 = q_view@crWq^T + bq -> hE
    k_hgemm<2><<<ggrid, gblk, GSMEM>>>(hA, wh + 4 * WN, hE, cr_bq, nullptr, nullptr);
    // 7. attn(Q2, KV, KV), output tokens bhw -> hB
    k_attn_h<true><<<B_ * W_ * NHEAD, 192, ATTN_SMEM>>>(hE, hC, hC, hB);
    // 8. CR = crattn@crWo^T -> hD (half, bhw order)
    k_hgemm<0><<<ggrid, gblk, GSMEM>>>(hB, wh + 5 * WN, hD, nullptr, nullptr, nullptr);
    // 9. depthwise+BN -> hA (half, token-major bhw)
    k_dwconv2<<<dgrid, 256>>>(x, dw_w, bn_g, bn_b, bn_m, bn_v, hA);
    // 10. out = clip(hA@pw^T,0,6) + CR(hD) -> BCHW fp32
    k_hgemm<3><<<ggrid, gblk, GSMEM>>>(hA, wh + 6 * WN, out, hD, nullptr, nullptr);
}